// round 10
// baseline (speedup 1.0000x reference)
#include <cuda_runtime.h>
#include <math.h>

#define T_TOK 8192
#define HDIM  1024
#define IDIM  3584
#define NEXP  8
#define MTILE 64
#define ROWCAP (2*T_TOK + NEXP*MTILE)   // 16896, every expert segment padded to 64
#define BK    32

// ---------------- scratch (static __device__, per harness rules) ----------------
__device__ float g_hbuf[(size_t)ROWCAP * IDIM];        // ~242 MB intermediate h
__device__ float g_outpair[2][T_TOK][HDIM];            // 64 MB per-slot outputs
__device__ int   g_rows[ROWCAP];                        // token | (slot<<16), -1 = pad
__device__ int   g_texp[T_TOK * 2];                     // chosen expert per (token,slot)
__device__ float g_topw[T_TOK * 2];                     // routing weight per (token,slot)
__device__ int   g_off[NEXP + 1];                       // padded segment offsets

// ---------------- f32x2 (FFMA2) helpers ----------------
__device__ __forceinline__ unsigned long long f2pack(float lo, float hi) {
    unsigned long long r;
    asm("mov.b64 %0, {%1, %2};" : "=l"(r) : "f"(lo), "f"(hi));
    return r;
}
__device__ __forceinline__ void f2unpack(unsigned long long v, float& lo, float& hi) {
    asm("mov.b64 {%0, %1}, %2;" : "=f"(lo), "=f"(hi) : "l"(v));
}
__device__ __forceinline__ unsigned long long f2fma(unsigned long long a,
                                                    unsigned long long b,
                                                    unsigned long long c) {
    unsigned long long d;
    asm("fma.rn.f32x2 %0, %1, %2, %3;" : "=l"(d) : "l"(a), "l"(b), "l"(c));
    return d;
}

// ---------------- 1) Router: logits -> softmax(fp32) -> top-2 (no renorm) ----------------
__global__ void router_kernel(const float* __restrict__ x,
                              const float* __restrict__ gw,
                              const float* __restrict__ gb) {
    __shared__ float sgw[NEXP * HDIM];  // 32 KB gate weights
    for (int i = threadIdx.x; i < NEXP * HDIM; i += blockDim.x) sgw[i] = gw[i];
    __syncthreads();

    int warp = (blockIdx.x * blockDim.x + threadIdx.x) >> 5;
    int lane = threadIdx.x & 31;
    if (warp >= T_TOK) return;

    const float* xr = x + (size_t)warp * HDIM;
    float acc[NEXP];
#pragma unroll
    for (int e = 0; e < NEXP; e++) acc[e] = 0.f;
    for (int k = lane; k < HDIM; k += 32) {
        float xv = xr[k];
#pragma unroll
        for (int e = 0; e < NEXP; e++) acc[e] = fmaf(xv, sgw[e * HDIM + k], acc[e]);
    }
#pragma unroll
    for (int e = 0; e < NEXP; e++) {
#pragma unroll
        for (int o = 16; o > 0; o >>= 1) acc[e] += __shfl_xor_sync(0xffffffffu, acc[e], o);
    }
    if (lane == 0) {
        float mx = -1e30f;
#pragma unroll
        for (int e = 0; e < NEXP; e++) { acc[e] += gb[e]; mx = fmaxf(mx, acc[e]); }
        float se = 0.f;
#pragma unroll
        for (int e = 0; e < NEXP; e++) { acc[e] = expf(acc[e] - mx); se += acc[e]; }
        float inv = 1.f / se;
        // top-2, ties -> lower index (matches lax.top_k)
        float b0 = -1.f, b1 = -1.f; int i0 = 0, i1 = 0;
#pragma unroll
        for (int e = 0; e < NEXP; e++) {
            float p = acc[e] * inv;
            if (p > b0)      { b1 = b0; i1 = i0; b0 = p; i0 = e; }
            else if (p > b1) { b1 = p;  i1 = e; }
        }
        g_texp[warp * 2 + 0] = i0;  g_texp[warp * 2 + 1] = i1;
        g_topw[warp * 2 + 0] = b0;  g_topw[warp * 2 + 1] = b1;
    }
}

// ---------------- 2) Build padded per-expert row lists (single block) ----------------
__global__ void build_lists_kernel() {
    __shared__ int cnt[NEXP], off[NEXP + 1], fill[NEXP];
    int tid = threadIdx.x;
    if (tid < NEXP) cnt[tid] = 0;
    __syncthreads();
    for (int i = tid; i < 2 * T_TOK; i += blockDim.x) atomicAdd(&cnt[g_texp[i]], 1);
    __syncthreads();
    if (tid == 0) {
        int o = 0;
        for (int e = 0; e < NEXP; e++) { off[e] = o; o += ((cnt[e] + MTILE - 1) / MTILE) * MTILE; }
        off[NEXP] = o;
    }
    __syncthreads();
    if (tid < NEXP)  fill[tid] = 0;
    if (tid <= NEXP) g_off[tid] = off[tid];
    for (int i = tid; i < ROWCAP; i += blockDim.x) g_rows[i] = -1;
    __syncthreads();
    for (int i = tid; i < 2 * T_TOK; i += blockDim.x) {
        int e = g_texp[i];
        int p = atomicAdd(&fill[e], 1);
        g_rows[off[e] + p] = (i >> 1) | ((i & 1) << 16);
    }
}

__device__ __forceinline__ int find_expert(int row0) {
    int e = 0;
#pragma unroll
    for (int q = 0; q < NEXP; q++)
        if (row0 >= g_off[q + 1]) e = q + 1;
    return e;
}

// ---------------- 3) GEMM1: h = silu(X@w1^T) * (X@w3^T), gathered rows ----------------
__global__ __launch_bounds__(256) void gemm1_kernel(const float* __restrict__ x,
                                                    const float* __restrict__ w1,
                                                    const float* __restrict__ w3) {
    __shared__ float As[BK][64];
    __shared__ float Bs1[BK][64];
    __shared__ float Bs3[BK][64];
    __shared__ int stok[64];

    int tid  = threadIdx.x;
    int row0 = blockIdx.y * MTILE;
    int n0   = blockIdx.x * 64;
    if (row0 >= g_off[NEXP]) return;
    int e = find_expert(row0);

    if (tid < 64) stok[tid] = g_rows[row0 + tid];
    __syncthreads();

    const float* B1g = w1 + (size_t)e * IDIM * HDIM;
    const float* B3g = w3 + (size_t)e * IDIM * HDIM;

    int ty = tid >> 4, tx = tid & 15;
    unsigned long long acc1[4][2], acc3[4][2];
#pragma unroll
    for (int i = 0; i < 4; i++) { acc1[i][0]=0ull; acc1[i][1]=0ull; acc3[i][0]=0ull; acc3[i][1]=0ull; }

    for (int k0 = 0; k0 < HDIM; k0 += BK) {
#pragma unroll
        for (int p = 0; p < 2; p++) {          // A tile 64x32 (gathered, transposed)
            int idx = tid + p * 256;
            int m = idx >> 3, kq = (idx & 7) << 2;
            int r = stok[m];
            float4 v = make_float4(0.f, 0.f, 0.f, 0.f);
            if (r >= 0) {
                int tok = r & 0xFFFF;
                v = *(const float4*)&x[(size_t)tok * HDIM + k0 + kq];
            }
            As[kq + 0][m] = v.x; As[kq + 1][m] = v.y; As[kq + 2][m] = v.z; As[kq + 3][m] = v.w;
        }
#pragma unroll
        for (int p = 0; p < 2; p++) {          // B1/B3 tiles 64x32 (transposed)
            int idx = tid + p * 256;
            int n = idx >> 3, kq = (idx & 7) << 2;
            float4 v1 = *(const float4*)&B1g[(size_t)(n0 + n) * HDIM + k0 + kq];
            float4 v3 = *(const float4*)&B3g[(size_t)(n0 + n) * HDIM + k0 + kq];
            Bs1[kq + 0][n] = v1.x; Bs1[kq + 1][n] = v1.y; Bs1[kq + 2][n] = v1.z; Bs1[kq + 3][n] = v1.w;
            Bs3[kq + 0][n] = v3.x; Bs3[kq + 1][n] = v3.y; Bs3[kq + 2][n] = v3.z; Bs3[kq + 3][n] = v3.w;
        }
        __syncthreads();
#pragma unroll 8
        for (int kk = 0; kk < BK; kk++) {
            float4 a4 = *(const float4*)&As[kk][ty * 4];
            unsigned long long ap0 = f2pack(a4.x, a4.x);
            unsigned long long ap1 = f2pack(a4.y, a4.y);
            unsigned long long ap2 = f2pack(a4.z, a4.z);
            unsigned long long ap3 = f2pack(a4.w, a4.w);
            ulonglong2 b1 = *(const ulonglong2*)&Bs1[kk][tx * 4];
            ulonglong2 b3 = *(const ulonglong2*)&Bs3[kk][tx * 4];
            acc1[0][0]=f2fma(ap0,b1.x,acc1[0][0]); acc1[0][1]=f2fma(ap0,b1.y,acc1[0][1]);
            acc3[0][0]=f2fma(ap0,b3.x,acc3[0][0]); acc3[0][1]=f2fma(ap0,b3.y,acc3[0][1]);
            acc1[1][0]=f2fma(ap1,b1.x,acc1[1][0]); acc1[1][1]=f2fma(ap1,b1.y,acc1[1][1]);
            acc3[1][0]=f2fma(ap1,b3.x,acc3[1][0]); acc3[1][1]=f2fma(ap1,b3.y,acc3[1][1]);
            acc1[2][0]=f2fma(ap2,b1.x,acc1[2][0]); acc1[2][1]=f2fma(ap2,b1.y,acc1[2][1]);
            acc3[2][0]=f2fma(ap2,b3.x,acc3[2][0]); acc3[2][1]=f2fma(ap2,b3.y,acc3[2][1]);
            acc1[3][0]=f2fma(ap3,b1.x,acc1[3][0]); acc1[3][1]=f2fma(ap3,b1.y,acc1[3][1]);
            acc3[3][0]=f2fma(ap3,b3.x,acc3[3][0]); acc3[3][1]=f2fma(ap3,b3.y,acc3[3][1]);
        }
        __syncthreads();
    }
    // epilogue: silu(c1) * c3  (pad rows have c1=c3=0 -> store 0, keeps hbuf clean)
#pragma unroll
    for (int i = 0; i < 4; i++) {
        float c1[4], c3[4];
        f2unpack(acc1[i][0], c1[0], c1[1]); f2unpack(acc1[i][1], c1[2], c1[3]);
        f2unpack(acc3[i][0], c3[0], c3[1]); f2unpack(acc3[i][1], c3[2], c3[3]);
        float4 hv;
        float* hp = (float*)&hv;
#pragma unroll
        for (int j = 0; j < 4; j++) {
            float s = c1[j] / (1.f + expf(-c1[j]));
            hp[j] = s * c3[j];
        }
        int m = ty * 4 + i;
        *(float4*)&g_hbuf[(size_t)(row0 + m) * IDIM + n0 + tx * 4] = hv;
    }
}

// ---------------- 4) GEMM2: out_pair[slot][tok] = w_tok * (h @ w2^T) ----------------
__global__ __launch_bounds__(256) void gemm2_kernel(const float* __restrict__ w2) {
    __shared__ float As[BK][64];
    __shared__ float Bs[BK][128];
    __shared__ int stok[64];

    int tid  = threadIdx.x;
    int row0 = blockIdx.y * MTILE;
    int n0   = blockIdx.x * 128;
    if (row0 >= g_off[NEXP]) return;
    int e = find_expert(row0);

    if (tid < 64) stok[tid] = g_rows[row0 + tid];

    const float* Bg = w2 + (size_t)e * HDIM * IDIM;
    int ty = tid >> 4, tx = tid & 15;
    unsigned long long acc[4][4];
#pragma unroll
    for (int i = 0; i < 4; i++)
#pragma unroll
        for (int j = 0; j < 4; j++) acc[i][j] = 0ull;

    for (int k0 = 0; k0 < IDIM; k0 += BK) {
#pragma unroll
        for (int p = 0; p < 2; p++) {          // A tile from hbuf (no gather)
            int idx = tid + p * 256;
            int m = idx >> 3, kq = (idx & 7) << 2;
            float4 v = *(const float4*)&g_hbuf[(size_t)(row0 + m) * IDIM + k0 + kq];
            As[kq + 0][m] = v.x; As[kq + 1][m] = v.y; As[kq + 2][m] = v.z; As[kq + 3][m] = v.w;
        }
#pragma unroll
        for (int p = 0; p < 4; p++) {          // B tile 128x32
            int idx = tid + p * 256;
            int n = idx >> 3, kq = (idx & 7) << 2;
            float4 v = *(const float4*)&Bg[(size_t)(n0 + n) * IDIM + k0 + kq];
            Bs[kq + 0][n] = v.x; Bs[kq + 1][n] = v.y; Bs[kq + 2][n] = v.z; Bs[kq + 3][n] = v.w;
        }
        __syncthreads();
#pragma unroll 8
        for (int kk = 0; kk < BK; kk++) {
            float4 a4 = *(const float4*)&As[kk][ty * 4];
            unsigned long long ap0 = f2pack(a4.x, a4.x);
            unsigned long long ap1 = f2pack(a4.y, a4.y);
            unsigned long long ap2 = f2pack(a4.z, a4.z);
            unsigned long long ap3 = f2pack(a4.w, a4.w);
            ulonglong2 bA = *(const ulonglong2*)&Bs[kk][tx * 8];
            ulonglong2 bB = *(const ulonglong2*)&Bs[kk][tx * 8 + 4];
            acc[0][0]=f2fma(ap0,bA.x,acc[0][0]); acc[0][1]=f2fma(ap0,bA.y,acc[0][1]);
            acc[0][2]=f2fma(ap0,bB.x,acc[0][2]); acc[0][3]=f2fma(ap0,bB.y,acc[0][3]);
            acc[1][0]=f2fma(ap1,bA.x,acc[1][0]); acc[1][1]=f2fma(ap1,bA.y,acc[1][1]);
            acc[1][2]=f2fma(ap1,bB.x,acc[1][2]); acc[1][3]=f2fma(ap1,bB.y,acc[1][3]);
            acc[2][0]=f2fma(ap2,bA.x,acc[2][0]); acc[2][1]=f2fma(ap2,bA.y,acc[2][1]);
            acc[2][2]=f2fma(ap2,bB.x,acc[2][2]); acc[2][3]=f2fma(ap2,bB.y,acc[2][3]);
            acc[3][0]=f2fma(ap3,bA.x,acc[3][0]); acc[3][1]=f2fma(ap3,bA.y,acc[3][1]);
            acc[3][2]=f2fma(ap3,bB.x,acc[3][2]); acc[3][3]=f2fma(ap3,bB.y,acc[3][3]);
        }
        __syncthreads();
    }
#pragma unroll
    for (int i = 0; i < 4; i++) {
        int r = stok[ty * 4 + i];
        if (r < 0) continue;                    // padding row
        int tok = r & 0xFFFF, slot = (r >> 16) & 1;
        float w = g_topw[tok * 2 + slot];
        float c[8];
        f2unpack(acc[i][0], c[0], c[1]); f2unpack(acc[i][1], c[2], c[3]);
        f2unpack(acc[i][2], c[4], c[5]); f2unpack(acc[i][3], c[6], c[7]);
        float4 o0 = make_float4(c[0]*w, c[1]*w, c[2]*w, c[3]*w);
        float4 o1 = make_float4(c[4]*w, c[5]*w, c[6]*w, c[7]*w);
        *(float4*)&g_outpair[slot][tok][n0 + tx * 8]     = o0;
        *(float4*)&g_outpair[slot][tok][n0 + tx * 8 + 4] = o1;
    }
}

// ---------------- 5) combine: out = slot0 + slot1 ----------------
__global__ void combine_kernel(float* __restrict__ out) {
    size_t i = (size_t)blockIdx.x * blockDim.x + threadIdx.x;
    const float4* p0 = (const float4*)&g_outpair[0][0][0];
    const float4* p1 = (const float4*)&g_outpair[1][0][0];
    float4 a = p0[i], b = p1[i];
    ((float4*)out)[i] = make_float4(a.x + b.x, a.y + b.y, a.z + b.z, a.w + b.w);
}

extern "C" void kernel_launch(void* const* d_in, const int* in_sizes, int n_in,
                              void* d_out, int out_size) {
    const float* x  = (const float*)d_in[0];
    const float* gw = (const float*)d_in[1];
    const float* gb = (const float*)d_in[2];
    const float* w1 = (const float*)d_in[3];
    const float* w2 = (const float*)d_in[4];
    const float* w3 = (const float*)d_in[5];
    float* out = (float*)d_out;

    router_kernel<<<T_TOK / 8, 256>>>(x, gw, gb);
    build_lists_kernel<<<1, 1024>>>();
    dim3 g1(IDIM / 64, ROWCAP / MTILE);   // (56, 264)
    gemm1_kernel<<<g1, 256>>>(x, w1, w3);
    dim3 g2(HDIM / 128, ROWCAP / MTILE);  // (8, 264)
    gemm2_kernel<<<g2, 256>>>(w2);
    combine_kernel<<<(T_TOK * HDIM / 4) / 256, 256>>>(out);
}

// round 11
// speedup vs baseline: 1.0021x; 1.0021x over previous
#include <cuda_runtime.h>
#include <math.h>

#define T_TOK 8192
#define HDIM  1024
#define IDIM  3584
#define NEXP  8
#define MTILE 64
#define ROWCAP (2*T_TOK + NEXP*MTILE)   // 16896, every expert segment padded to 64
#define BK    32

// ---------------- scratch (static __device__, per harness rules) ----------------
__device__ float g_hbuf[(size_t)ROWCAP * IDIM];        // ~242 MB intermediate h
__device__ float g_outpair[2][T_TOK][HDIM];            // 64 MB per-slot outputs
__device__ int   g_rows[ROWCAP];                        // token | (slot<<16), -1 = pad
__device__ int   g_texp[T_TOK * 2];                     // chosen expert per (token,slot)
__device__ float g_topw[T_TOK * 2];                     // routing weight per (token,slot)
__device__ int   g_off[NEXP + 1];                       // padded segment offsets

// ---------------- f32x2 (FFMA2) helpers ----------------
__device__ __forceinline__ unsigned long long f2pack(float lo, float hi) {
    unsigned long long r;
    asm("mov.b64 %0, {%1, %2};" : "=l"(r) : "f"(lo), "f"(hi));
    return r;
}
__device__ __forceinline__ void f2unpack(unsigned long long v, float& lo, float& hi) {
    asm("mov.b64 {%0, %1}, %2;" : "=f"(lo), "=f"(hi) : "l"(v));
}
__device__ __forceinline__ unsigned long long f2fma(unsigned long long a,
                                                    unsigned long long b,
                                                    unsigned long long c) {
    unsigned long long d;
    asm("fma.rn.f32x2 %0, %1, %2, %3;" : "=l"(d) : "l"(a), "l"(b), "l"(c));
    return d;
}

// ---------------- 1) Router: logits -> softmax(fp32) -> top-2 (no renorm) ----------------
__global__ void router_kernel(const float* __restrict__ x,
                              const float* __restrict__ gw,
                              const float* __restrict__ gb) {
    __shared__ float sgw[NEXP * HDIM];  // 32 KB gate weights
    for (int i = threadIdx.x; i < NEXP * HDIM; i += blockDim.x) sgw[i] = gw[i];
    __syncthreads();

    int warp = (blockIdx.x * blockDim.x + threadIdx.x) >> 5;
    int lane = threadIdx.x & 31;
    if (warp >= T_TOK) return;

    const float* xr = x + (size_t)warp * HDIM;
    float acc[NEXP];
#pragma unroll
    for (int e = 0; e < NEXP; e++) acc[e] = 0.f;
    for (int k = lane; k < HDIM; k += 32) {
        float xv = xr[k];
#pragma unroll
        for (int e = 0; e < NEXP; e++) acc[e] = fmaf(xv, sgw[e * HDIM + k], acc[e]);
    }
#pragma unroll
    for (int e = 0; e < NEXP; e++) {
#pragma unroll
        for (int o = 16; o > 0; o >>= 1) acc[e] += __shfl_xor_sync(0xffffffffu, acc[e], o);
    }
    if (lane == 0) {
        float mx = -1e30f;
#pragma unroll
        for (int e = 0; e < NEXP; e++) { acc[e] += gb[e]; mx = fmaxf(mx, acc[e]); }
        float se = 0.f;
#pragma unroll
        for (int e = 0; e < NEXP; e++) { acc[e] = expf(acc[e] - mx); se += acc[e]; }
        float inv = 1.f / se;
        // top-2, ties -> lower index (matches lax.top_k)
        float b0 = -1.f, b1 = -1.f; int i0 = 0, i1 = 0;
#pragma unroll
        for (int e = 0; e < NEXP; e++) {
            float p = acc[e] * inv;
            if (p > b0)      { b1 = b0; i1 = i0; b0 = p; i0 = e; }
            else if (p > b1) { b1 = p;  i1 = e; }
        }
        g_texp[warp * 2 + 0] = i0;  g_texp[warp * 2 + 1] = i1;
        g_topw[warp * 2 + 0] = b0;  g_topw[warp * 2 + 1] = b1;
    }
}

// ---------------- 2) Build padded per-expert row lists (single block) ----------------
__global__ void build_lists_kernel() {
    __shared__ int cnt[NEXP], off[NEXP + 1], fill[NEXP];
    int tid = threadIdx.x;
    if (tid < NEXP) cnt[tid] = 0;
    __syncthreads();
    for (int i = tid; i < 2 * T_TOK; i += blockDim.x) atomicAdd(&cnt[g_texp[i]], 1);
    __syncthreads();
    if (tid == 0) {
        int o = 0;
        for (int e = 0; e < NEXP; e++) { off[e] = o; o += ((cnt[e] + MTILE - 1) / MTILE) * MTILE; }
        off[NEXP] = o;
    }
    __syncthreads();
    if (tid < NEXP)  fill[tid] = 0;
    if (tid <= NEXP) g_off[tid] = off[tid];
    for (int i = tid; i < ROWCAP; i += blockDim.x) g_rows[i] = -1;
    __syncthreads();
    for (int i = tid; i < 2 * T_TOK; i += blockDim.x) {
        int e = g_texp[i];
        int p = atomicAdd(&fill[e], 1);
        g_rows[off[e] + p] = (i >> 1) | ((i & 1) << 16);
    }
}

__device__ __forceinline__ int find_expert(int row0) {
    int e = 0;
#pragma unroll
    for (int q = 0; q < NEXP; q++)
        if (row0 >= g_off[q + 1]) e = q + 1;
    return e;
}

// ---------------- 3) GEMM1: h = silu(X@w1^T) * (X@w3^T), gathered rows ----------------
__global__ __launch_bounds__(256) void gemm1_kernel(const float* __restrict__ x,
                                                    const float* __restrict__ w1,
                                                    const float* __restrict__ w3) {
    __shared__ float As[BK][64];
    __shared__ float Bs1[BK][64];
    __shared__ float Bs3[BK][64];
    __shared__ int stok[64];

    int tid  = threadIdx.x;
    int row0 = blockIdx.y * MTILE;
    int n0   = blockIdx.x * 64;
    if (row0 >= g_off[NEXP]) return;
    int e = find_expert(row0);

    if (tid < 64) stok[tid] = g_rows[row0 + tid];
    __syncthreads();

    const float* B1g = w1 + (size_t)e * IDIM * HDIM;
    const float* B3g = w3 + (size_t)e * IDIM * HDIM;

    int ty = tid >> 4, tx = tid & 15;
    unsigned long long acc1[4][2], acc3[4][2];
#pragma unroll
    for (int i = 0; i < 4; i++) { acc1[i][0]=0ull; acc1[i][1]=0ull; acc3[i][0]=0ull; acc3[i][1]=0ull; }

    for (int k0 = 0; k0 < HDIM; k0 += BK) {
#pragma unroll
        for (int p = 0; p < 2; p++) {          // A tile 64x32 (gathered, transposed)
            int idx = tid + p * 256;
            int m = idx >> 3, kq = (idx & 7) << 2;
            int r = stok[m];
            float4 v = make_float4(0.f, 0.f, 0.f, 0.f);
            if (r >= 0) {
                int tok = r & 0xFFFF;
                v = *(const float4*)&x[(size_t)tok * HDIM + k0 + kq];
            }
            As[kq + 0][m] = v.x; As[kq + 1][m] = v.y; As[kq + 2][m] = v.z; As[kq + 3][m] = v.w;
        }
#pragma unroll
        for (int p = 0; p < 2; p++) {          // B1/B3 tiles 64x32 (transposed)
            int idx = tid + p * 256;
            int n = idx >> 3, kq = (idx & 7) << 2;
            float4 v1 = *(const float4*)&B1g[(size_t)(n0 + n) * HDIM + k0 + kq];
            float4 v3 = *(const float4*)&B3g[(size_t)(n0 + n) * HDIM + k0 + kq];
            Bs1[kq + 0][n] = v1.x; Bs1[kq + 1][n] = v1.y; Bs1[kq + 2][n] = v1.z; Bs1[kq + 3][n] = v1.w;
            Bs3[kq + 0][n] = v3.x; Bs3[kq + 1][n] = v3.y; Bs3[kq + 2][n] = v3.z; Bs3[kq + 3][n] = v3.w;
        }
        __syncthreads();
#pragma unroll 8
        for (int kk = 0; kk < BK; kk++) {
            float4 a4 = *(const float4*)&As[kk][ty * 4];
            unsigned long long ap0 = f2pack(a4.x, a4.x);
            unsigned long long ap1 = f2pack(a4.y, a4.y);
            unsigned long long ap2 = f2pack(a4.z, a4.z);
            unsigned long long ap3 = f2pack(a4.w, a4.w);
            ulonglong2 b1 = *(const ulonglong2*)&Bs1[kk][tx * 4];
            ulonglong2 b3 = *(const ulonglong2*)&Bs3[kk][tx * 4];
            acc1[0][0]=f2fma(ap0,b1.x,acc1[0][0]); acc1[0][1]=f2fma(ap0,b1.y,acc1[0][1]);
            acc3[0][0]=f2fma(ap0,b3.x,acc3[0][0]); acc3[0][1]=f2fma(ap0,b3.y,acc3[0][1]);
            acc1[1][0]=f2fma(ap1,b1.x,acc1[1][0]); acc1[1][1]=f2fma(ap1,b1.y,acc1[1][1]);
            acc3[1][0]=f2fma(ap1,b3.x,acc3[1][0]); acc3[1][1]=f2fma(ap1,b3.y,acc3[1][1]);
            acc1[2][0]=f2fma(ap2,b1.x,acc1[2][0]); acc1[2][1]=f2fma(ap2,b1.y,acc1[2][1]);
            acc3[2][0]=f2fma(ap2,b3.x,acc3[2][0]); acc3[2][1]=f2fma(ap2,b3.y,acc3[2][1]);
            acc1[3][0]=f2fma(ap3,b1.x,acc1[3][0]); acc1[3][1]=f2fma(ap3,b1.y,acc1[3][1]);
            acc3[3][0]=f2fma(ap3,b3.x,acc3[3][0]); acc3[3][1]=f2fma(ap3,b3.y,acc3[3][1]);
        }
        __syncthreads();
    }
    // epilogue: silu(c1) * c3  (pad rows have c1=c3=0 -> store 0, keeps hbuf clean)
#pragma unroll
    for (int i = 0; i < 4; i++) {
        float c1[4], c3[4];
        f2unpack(acc1[i][0], c1[0], c1[1]); f2unpack(acc1[i][1], c1[2], c1[3]);
        f2unpack(acc3[i][0], c3[0], c3[1]); f2unpack(acc3[i][1], c3[2], c3[3]);
        float4 hv;
        float* hp = (float*)&hv;
#pragma unroll
        for (int j = 0; j < 4; j++) {
            float s = c1[j] / (1.f + expf(-c1[j]));
            hp[j] = s * c3[j];
        }
        int m = ty * 4 + i;
        *(float4*)&g_hbuf[(size_t)(row0 + m) * IDIM + n0 + tx * 4] = hv;
    }
}

// ---------------- 4) GEMM2: out_pair[slot][tok] = w_tok * (h @ w2^T) ----------------
__global__ __launch_bounds__(256) void gemm2_kernel(const float* __restrict__ w2) {
    __shared__ float As[BK][64];
    __shared__ float Bs[BK][128];
    __shared__ int stok[64];

    int tid  = threadIdx.x;
    int row0 = blockIdx.y * MTILE;
    int n0   = blockIdx.x * 128;
    if (row0 >= g_off[NEXP]) return;
    int e = find_expert(row0);

    if (tid < 64) stok[tid] = g_rows[row0 + tid];

    const float* Bg = w2 + (size_t)e * HDIM * IDIM;
    int ty = tid >> 4, tx = tid & 15;
    unsigned long long acc[4][4];
#pragma unroll
    for (int i = 0; i < 4; i++)
#pragma unroll
        for (int j = 0; j < 4; j++) acc[i][j] = 0ull;

    for (int k0 = 0; k0 < IDIM; k0 += BK) {
#pragma unroll
        for (int p = 0; p < 2; p++) {          // A tile from hbuf (no gather)
            int idx = tid + p * 256;
            int m = idx >> 3, kq = (idx & 7) << 2;
            float4 v = *(const float4*)&g_hbuf[(size_t)(row0 + m) * IDIM + k0 + kq];
            As[kq + 0][m] = v.x; As[kq + 1][m] = v.y; As[kq + 2][m] = v.z; As[kq + 3][m] = v.w;
        }
#pragma unroll
        for (int p = 0; p < 4; p++) {          // B tile 128x32
            int idx = tid + p * 256;
            int n = idx >> 3, kq = (idx & 7) << 2;
            float4 v = *(const float4*)&Bg[(size_t)(n0 + n) * IDIM + k0 + kq];
            Bs[kq + 0][n] = v.x; Bs[kq + 1][n] = v.y; Bs[kq + 2][n] = v.z; Bs[kq + 3][n] = v.w;
        }
        __syncthreads();
#pragma unroll 8
        for (int kk = 0; kk < BK; kk++) {
            float4 a4 = *(const float4*)&As[kk][ty * 4];
            unsigned long long ap0 = f2pack(a4.x, a4.x);
            unsigned long long ap1 = f2pack(a4.y, a4.y);
            unsigned long long ap2 = f2pack(a4.z, a4.z);
            unsigned long long ap3 = f2pack(a4.w, a4.w);
            ulonglong2 bA = *(const ulonglong2*)&Bs[kk][tx * 8];
            ulonglong2 bB = *(const ulonglong2*)&Bs[kk][tx * 8 + 4];
            acc[0][0]=f2fma(ap0,bA.x,acc[0][0]); acc[0][1]=f2fma(ap0,bA.y,acc[0][1]);
            acc[0][2]=f2fma(ap0,bB.x,acc[0][2]); acc[0][3]=f2fma(ap0,bB.y,acc[0][3]);
            acc[1][0]=f2fma(ap1,bA.x,acc[1][0]); acc[1][1]=f2fma(ap1,bA.y,acc[1][1]);
            acc[1][2]=f2fma(ap1,bB.x,acc[1][2]); acc[1][3]=f2fma(ap1,bB.y,acc[1][3]);
            acc[2][0]=f2fma(ap2,bA.x,acc[2][0]); acc[2][1]=f2fma(ap2,bA.y,acc[2][1]);
            acc[2][2]=f2fma(ap2,bB.x,acc[2][2]); acc[2][3]=f2fma(ap2,bB.y,acc[2][3]);
            acc[3][0]=f2fma(ap3,bA.x,acc[3][0]); acc[3][1]=f2fma(ap3,bA.y,acc[3][1]);
            acc[3][2]=f2fma(ap3,bB.x,acc[3][2]); acc[3][3]=f2fma(ap3,bB.y,acc[3][3]);
        }
        __syncthreads();
    }
#pragma unroll
    for (int i = 0; i < 4; i++) {
        int r = stok[ty * 4 + i];
        if (r < 0) continue;                    // padding row
        int tok = r & 0xFFFF, slot = (r >> 16) & 1;
        float w = g_topw[tok * 2 + slot];
        float c[8];
        f2unpack(acc[i][0], c[0], c[1]); f2unpack(acc[i][1], c[2], c[3]);
        f2unpack(acc[i][2], c[4], c[5]); f2unpack(acc[i][3], c[6], c[7]);
        float4 o0 = make_float4(c[0]*w, c[1]*w, c[2]*w, c[3]*w);
        float4 o1 = make_float4(c[4]*w, c[5]*w, c[6]*w, c[7]*w);
        *(float4*)&g_outpair[slot][tok][n0 + tx * 8]     = o0;
        *(float4*)&g_outpair[slot][tok][n0 + tx * 8 + 4] = o1;
    }
}

// ---------------- 5) combine: out = slot0 + slot1 ----------------
__global__ void combine_kernel(float* __restrict__ out) {
    size_t i = (size_t)blockIdx.x * blockDim.x + threadIdx.x;
    const float4* p0 = (const float4*)&g_outpair[0][0][0];
    const float4* p1 = (const float4*)&g_outpair[1][0][0];
    float4 a = p0[i], b = p1[i];
    ((float4*)out)[i] = make_float4(a.x + b.x, a.y + b.y, a.z + b.z, a.w + b.w);
}

extern "C" void kernel_launch(void* const* d_in, const int* in_sizes, int n_in,
                              void* d_out, int out_size) {
    const float* x  = (const float*)d_in[0];
    const float* gw = (const float*)d_in[1];
    const float* gb = (const float*)d_in[2];
    const float* w1 = (const float*)d_in[3];
    const float* w2 = (const float*)d_in[4];
    const float* w3 = (const float*)d_in[5];
    float* out = (float*)d_out;

    router_kernel<<<T_TOK / 8, 256>>>(x, gw, gb);
    build_lists_kernel<<<1, 1024>>>();
    dim3 g1(IDIM / 64, ROWCAP / MTILE);   // (56, 264)
    gemm1_kernel<<<g1, 256>>>(x, w1, w3);
    dim3 g2(HDIM / 128, ROWCAP / MTILE);  // (8, 264)
    gemm2_kernel<<<g2, 256>>>(w2);
    combine_kernel<<<(T_TOK * HDIM / 4) / 256, 256>>>(out);
}

// round 15
// speedup vs baseline: 3.2701x; 3.2632x over previous
#include <cuda_runtime.h>
#include <cuda_bf16.h>
#include <math.h>
#include <stdint.h>

#define T_TOK 8192
#define HDIM  1024
#define IDIM  3584
#define NEXP  8
#define MT    128
#define ROWCAP (2*T_TOK + NEXP*MT)     // 17408
#define NW    (NEXP*IDIM*HDIM)         // 29360128 elems per weight tensor

// ---------------- static scratch ----------------
__device__ __align__(128) __nv_bfloat16 g_w1h[NW], g_w1l[NW];
__device__ __align__(128) __nv_bfloat16 g_w3h[NW], g_w3l[NW];
__device__ __align__(128) __nv_bfloat16 g_w2h[NW], g_w2l[NW];
__device__ __align__(128) __nv_bfloat16 g_ah[(size_t)ROWCAP * HDIM], g_al[(size_t)ROWCAP * HDIM];
__device__ __align__(128) __nv_bfloat16 g_hh[(size_t)ROWCAP * IDIM], g_hl[(size_t)ROWCAP * IDIM];
__device__ float g_outpair[2][T_TOK][HDIM];
__device__ int   g_rows[ROWCAP];        // token | (slot<<16), -1 = pad
__device__ int   g_texp[T_TOK * 2];
__device__ float g_topw[T_TOK * 2];
__device__ int   g_off[NEXP + 1];

// ---------------- helpers (compute_80-era PTX only: mma.sync / ldmatrix / cp.async) ----------------
__device__ __forceinline__ uint32_t smem_u32(const void* p) {
    uint32_t a;
    asm("{ .reg .u64 t; cvta.to.shared.u64 t, %1; cvt.u32.u64 %0, t; }" : "=r"(a) : "l"(p));
    return a;
}
__device__ __forceinline__ void cpasync16(uint32_t dst, const void* src) {
    asm volatile("cp.async.cg.shared.global [%0], [%1], 16;" :: "r"(dst), "l"(src));
}
__device__ __forceinline__ void cp_commit() {
    asm volatile("cp.async.commit_group;" ::: "memory");
}
template<int N>
__device__ __forceinline__ void cp_wait() {
    asm volatile("cp.async.wait_group %0;" :: "n"(N) : "memory");
}
__device__ __forceinline__ void ldsm4(uint32_t* r, uint32_t addr) {
    asm volatile("ldmatrix.sync.aligned.m8n8.x4.shared.b16 {%0,%1,%2,%3}, [%4];"
                 : "=r"(r[0]), "=r"(r[1]), "=r"(r[2]), "=r"(r[3]) : "r"(addr));
}
__device__ __forceinline__ void mma_bf16(float* d, const uint32_t* a, const uint32_t* b) {
    asm volatile("mma.sync.aligned.m16n8k16.row.col.f32.bf16.bf16.f32 "
                 "{%0,%1,%2,%3}, {%4,%5,%6,%7}, {%8,%9}, {%0,%1,%2,%3};"
                 : "+f"(d[0]), "+f"(d[1]), "+f"(d[2]), "+f"(d[3])
                 : "r"(a[0]), "r"(a[1]), "r"(a[2]), "r"(a[3]), "r"(b[0]), "r"(b[1]));
}
__device__ __forceinline__ void split_pair(float a, float b, __nv_bfloat162& hi, __nv_bfloat162& lo) {
    __nv_bfloat16 ah = __float2bfloat16(a);
    __nv_bfloat16 bh = __float2bfloat16(b);
    __nv_bfloat16 al = __float2bfloat16(a - __bfloat162float(ah));
    __nv_bfloat16 bl = __float2bfloat16(b - __bfloat162float(bh));
    hi = __halves2bfloat162(ah, bh);
    lo = __halves2bfloat162(al, bl);
}
__device__ __forceinline__ int find_expert(int row0) {
    int e = 0;
#pragma unroll
    for (int q = 0; q < NEXP; q++)
        if (row0 >= g_off[q + 1]) e = q + 1;
    return e;
}

#define STAGES      3
#define STAGE_BYTES 32768            // A 16KB + B 16KB
#define SMEM_BYTES  (STAGES * STAGE_BYTES)

// ---------------- 0) fp32 -> bf16 hi/lo split of all weights ----------------
__global__ void convert_weights(const float* __restrict__ w1,
                                const float* __restrict__ w2,
                                const float* __restrict__ w3) {
    const size_t QT = NW / 4;
    size_t q = (size_t)blockIdx.x * blockDim.x + threadIdx.x;
    if (q >= 3 * QT) return;
    const float* src; __nv_bfloat16 *dh, *dl;
    size_t j = q;
    if (j < QT)           { src = w1; dh = g_w1h; dl = g_w1l; }
    else if (j < 2 * QT)  { j -= QT;     src = w3; dh = g_w3h; dl = g_w3l; }
    else                  { j -= 2 * QT; src = w2; dh = g_w2h; dl = g_w2l; }
    float4 v = ((const float4*)src)[j];
    __nv_bfloat162 h0, l0, h1, l1;
    split_pair(v.x, v.y, h0, l0);
    split_pair(v.z, v.w, h1, l1);
    ((__nv_bfloat162*)dh)[2 * j]     = h0;
    ((__nv_bfloat162*)dh)[2 * j + 1] = h1;
    ((__nv_bfloat162*)dl)[2 * j]     = l0;
    ((__nv_bfloat162*)dl)[2 * j + 1] = l1;
}

// ---------------- 1) Router ----------------
__global__ void router_kernel(const float* __restrict__ x,
                              const float* __restrict__ gw,
                              const float* __restrict__ gb) {
    __shared__ float sgw[NEXP * HDIM];
    for (int i = threadIdx.x; i < NEXP * HDIM; i += blockDim.x) sgw[i] = gw[i];
    __syncthreads();

    int warp = (blockIdx.x * blockDim.x + threadIdx.x) >> 5;
    int lane = threadIdx.x & 31;
    if (warp >= T_TOK) return;

    const float* xr = x + (size_t)warp * HDIM;
    float acc[NEXP];
#pragma unroll
    for (int e = 0; e < NEXP; e++) acc[e] = 0.f;
    for (int k = lane; k < HDIM; k += 32) {
        float xv = xr[k];
#pragma unroll
        for (int e = 0; e < NEXP; e++) acc[e] = fmaf(xv, sgw[e * HDIM + k], acc[e]);
    }
#pragma unroll
    for (int e = 0; e < NEXP; e++) {
#pragma unroll
        for (int o = 16; o > 0; o >>= 1) acc[e] += __shfl_xor_sync(0xffffffffu, acc[e], o);
    }
    if (lane == 0) {
        float mx = -1e30f;
#pragma unroll
        for (int e = 0; e < NEXP; e++) { acc[e] += gb[e]; mx = fmaxf(mx, acc[e]); }
        float se = 0.f;
#pragma unroll
        for (int e = 0; e < NEXP; e++) { acc[e] = expf(acc[e] - mx); se += acc[e]; }
        float inv = 1.f / se;
        float b0 = -1.f, b1 = -1.f; int i0 = 0, i1 = 0;
#pragma unroll
        for (int e = 0; e < NEXP; e++) {
            float p = acc[e] * inv;
            if (p > b0)      { b1 = b0; i1 = i0; b0 = p; i0 = e; }
            else if (p > b1) { b1 = p;  i1 = e; }
        }
        g_texp[warp * 2 + 0] = i0;  g_texp[warp * 2 + 1] = i1;
        g_topw[warp * 2 + 0] = b0;  g_topw[warp * 2 + 1] = b1;
    }
}

// ---------------- 2) Build 128-padded per-expert row lists ----------------
__global__ void build_lists_kernel() {
    __shared__ int cnt[NEXP], off[NEXP + 1], fill[NEXP];
    int tid = threadIdx.x;
    if (tid < NEXP) cnt[tid] = 0;
    __syncthreads();
    for (int i = tid; i < 2 * T_TOK; i += blockDim.x) atomicAdd(&cnt[g_texp[i]], 1);
    __syncthreads();
    if (tid == 0) {
        int o = 0;
        for (int e = 0; e < NEXP; e++) { off[e] = o; o += ((cnt[e] + MT - 1) / MT) * MT; }
        off[NEXP] = o;
    }
    __syncthreads();
    if (tid < NEXP)  fill[tid] = 0;
    if (tid <= NEXP) g_off[tid] = off[tid];
    for (int i = tid; i < ROWCAP; i += blockDim.x) g_rows[i] = -1;
    __syncthreads();
    for (int i = tid; i < 2 * T_TOK; i += blockDim.x) {
        int e = g_texp[i];
        int p = atomicAdd(&fill[e], 1);
        g_rows[off[e] + p] = (i >> 1) | ((i & 1) << 16);
    }
}

// ---------------- 3) gather+split activations ----------------
__global__ void gather_a(const float* __restrict__ x) {
    int row = blockIdx.x;
    int t = threadIdx.x;
    int r = g_rows[row];
    float4 v = make_float4(0.f, 0.f, 0.f, 0.f);
    if (r >= 0) v = ((const float4*)(x + (size_t)(r & 0xFFFF) * HDIM))[t];
    __nv_bfloat162 h0, l0, h1, l1;
    split_pair(v.x, v.y, h0, l0);
    split_pair(v.z, v.w, h1, l1);
    size_t base = (size_t)row * (HDIM / 2) + t * 2;
    ((__nv_bfloat162*)g_ah)[base]     = h0;
    ((__nv_bfloat162*)g_ah)[base + 1] = h1;
    ((__nv_bfloat162*)g_al)[base]     = l0;
    ((__nv_bfloat162*)g_al)[base + 1] = l1;
}

// smem tile layout (per stage): A at +0: 128 rows x 128B (bytes [0,64)=hi k0..31,
// [64,128)=lo). B at +16384 same. 16B chunk c stored at c ^ (row&7)  (Swizzle<3,4,3>).
#define SWOFF(row, c) ((uint32_t)((row) * 128 + (((c) ^ ((row) & 7)) << 4)))

// ---------------- 4) GEMM1 (mma.sync): h = silu(A@w1^T) * (A@w3^T) ----------------
__global__ __launch_bounds__(256, 1) void gemm1_mma() {
    extern __shared__ char smem[];
    const uint32_t sb = smem_u32(smem);
    const int tid = threadIdx.x;
    const int row0 = blockIdx.y * MT;
    const int n0   = blockIdx.x * 64;          // 64 I-cols per CTA
    if (row0 >= g_off[NEXP]) return;
    const int e = find_expert(row0);

    const __nv_bfloat16* Ah = g_ah + (size_t)row0 * HDIM;
    const __nv_bfloat16* Al = g_al + (size_t)row0 * HDIM;
    const size_t wb = ((size_t)e * IDIM + n0) * HDIM;
    const __nv_bfloat16* W1h = g_w1h + wb;
    const __nv_bfloat16* W1l = g_w1l + wb;
    const __nv_bfloat16* W3h = g_w3h + wb;
    const __nv_bfloat16* W3l = g_w3l + wb;

    auto load_stage = [&](int s) {
        const int bi = s % STAGES;
        const uint32_t dA = sb + bi * STAGE_BYTES;
        const uint32_t dB = dA + 16384;
        const int k0 = s * 32;
#pragma unroll
        for (int i = 0; i < 4; i++) {          // A: 1024 16B chunks
            int idx = tid + i * 256;
            int r = idx >> 3, c = idx & 7;
            const __nv_bfloat16* src = ((c < 4) ? Ah : Al) + (size_t)r * HDIM + k0 + (c & 3) * 8;
            cpasync16(dA + SWOFF(r, c), src);
        }
#pragma unroll
        for (int i = 0; i < 4; i++) {          // B: rows 0-63 w1, 64-127 w3
            int idx = tid + i * 256;
            int r = idx >> 3, c = idx & 7;
            int rr = r & 63;
            const __nv_bfloat16* mh = (r < 64) ? W1h : W3h;
            const __nv_bfloat16* ml = (r < 64) ? W1l : W3l;
            const __nv_bfloat16* src = ((c < 4) ? mh : ml) + (size_t)rr * HDIM + k0 + (c & 3) * 8;
            cpasync16(dB + SWOFF(r, c), src);
        }
        cp_commit();
    };

    const int lane = tid & 31, w = tid >> 5;
    const int mw = w >> 2, nw = w & 3;
    const int lrow = lane & 15, lkc = lane >> 4;

    float c1[4][2][4] = {}, c3[4][2][4] = {};

    const int NK = HDIM / 32;                  // 32
    load_stage(0); load_stage(1);

    for (int i = 0; i < NK; i++) {
        if (i + 2 < NK) cp_wait<1>(); else cp_wait<0>();
        __syncthreads();
        if (i + 2 < NK) load_stage(i + 2);

        const uint32_t Ab = sb + (i % STAGES) * STAGE_BYTES;
        const uint32_t Bb = Ab + 16384;
#pragma unroll
        for (int ks = 0; ks < 2; ks++) {
            const int kch = ks * 2 + lkc;      // hi plane chunk
            const int kcl = 4 + ks * 2 + lkc;  // lo plane chunk
            uint32_t aH[4][4], aL[4][4];
#pragma unroll
            for (int mt = 0; mt < 4; mt++) {
                int row = mw * 64 + mt * 16 + lrow;
                ldsm4(aH[mt], Ab + SWOFF(row, kch));
                ldsm4(aL[mt], Ab + SWOFF(row, kcl));
            }
            // B fragments: K-major storage + row.col mma -> NON-trans ldmatrix
            uint32_t b1h[4], b1l[4], b3h[4], b3l[4];
            {
                int br1 = nw * 16 + lrow;
                int br3 = 64 + nw * 16 + lrow;
                ldsm4(b1h, Bb + SWOFF(br1, kch));
                ldsm4(b1l, Bb + SWOFF(br1, kcl));
                ldsm4(b3h, Bb + SWOFF(br3, kch));
                ldsm4(b3l, Bb + SWOFF(br3, kcl));
            }
#pragma unroll
            for (int mt = 0; mt < 4; mt++) {
#pragma unroll
                for (int nt = 0; nt < 2; nt++) {
                    uint32_t f1h[2] = { b1h[nt], b1h[nt + 2] };
                    uint32_t f1l[2] = { b1l[nt], b1l[nt + 2] };
                    mma_bf16(c1[mt][nt], aH[mt], f1h);
                    mma_bf16(c1[mt][nt], aH[mt], f1l);
                    mma_bf16(c1[mt][nt], aL[mt], f1h);
                    uint32_t f3h[2] = { b3h[nt], b3h[nt + 2] };
                    uint32_t f3l[2] = { b3l[nt], b3l[nt + 2] };
                    mma_bf16(c3[mt][nt], aH[mt], f3h);
                    mma_bf16(c3[mt][nt], aH[mt], f3l);
                    mma_bf16(c3[mt][nt], aL[mt], f3h);
                }
            }
        }
    }

    // epilogue: silu(c1)*c3 -> bf16 hi/lo planes of h
    const int g = lane >> 2, tig = lane & 3;
#pragma unroll
    for (int mt = 0; mt < 4; mt++) {
#pragma unroll
        for (int nt = 0; nt < 2; nt++) {
            int icol = n0 + nw * 16 + nt * 8 + tig * 2;
#pragma unroll
            for (int hh = 0; hh < 2; hh++) {
                size_t m = (size_t)(row0 + mw * 64 + mt * 16 + g + hh * 8);
                float v1a = c1[mt][nt][hh * 2],     v3a = c3[mt][nt][hh * 2];
                float v1b = c1[mt][nt][hh * 2 + 1], v3b = c3[mt][nt][hh * 2 + 1];
                float ha = v1a / (1.f + expf(-v1a)) * v3a;
                float hb = v1b / (1.f + expf(-v1b)) * v3b;
                __nv_bfloat162 hi, lo;
                split_pair(ha, hb, hi, lo);
                *(__nv_bfloat162*)&g_hh[m * IDIM + icol] = hi;
                *(__nv_bfloat162*)&g_hl[m * IDIM + icol] = lo;
            }
        }
    }
}

// ---------------- 5) GEMM2 (mma.sync): outpair = w * (h @ w2^T) ----------------
__global__ __launch_bounds__(256, 1) void gemm2_mma() {
    extern __shared__ char smem[];
    const uint32_t sb = smem_u32(smem);
    const int tid = threadIdx.x;
    const int row0 = blockIdx.y * MT;
    const int n0   = blockIdx.x * 128;         // 128 H-cols per CTA
    if (row0 >= g_off[NEXP]) return;
    const int e = find_expert(row0);

    const __nv_bfloat16* Ahp = g_hh + (size_t)row0 * IDIM;
    const __nv_bfloat16* Alp = g_hl + (size_t)row0 * IDIM;
    const size_t wb = ((size_t)e * HDIM + n0) * IDIM;
    const __nv_bfloat16* Bh = g_w2h + wb;
    const __nv_bfloat16* Bl = g_w2l + wb;

    auto load_stage = [&](int s) {
        const int bi = s % STAGES;
        const uint32_t dA = sb + bi * STAGE_BYTES;
        const uint32_t dB = dA + 16384;
        const int k0 = s * 32;
#pragma unroll
        for (int i = 0; i < 4; i++) {
            int idx = tid + i * 256;
            int r = idx >> 3, c = idx & 7;
            const __nv_bfloat16* src = ((c < 4) ? Ahp : Alp) + (size_t)r * IDIM + k0 + (c & 3) * 8;
            cpasync16(dA + SWOFF(r, c), src);
        }
#pragma unroll
        for (int i = 0; i < 4; i++) {
            int idx = tid + i * 256;
            int r = idx >> 3, c = idx & 7;
            const __nv_bfloat16* src = ((c < 4) ? Bh : Bl) + (size_t)r * IDIM + k0 + (c & 3) * 8;
            cpasync16(dB + SWOFF(r, c), src);
        }
        cp_commit();
    };

    const int lane = tid & 31, w = tid >> 5;
    const int mw = w >> 2, nw = w & 3;
    const int lrow = lane & 15, lkc = lane >> 4;

    float acc[4][4][4] = {};

    const int NK = IDIM / 32;                  // 112
    load_stage(0); load_stage(1);

    for (int i = 0; i < NK; i++) {
        if (i + 2 < NK) cp_wait<1>(); else cp_wait<0>();
        __syncthreads();
        if (i + 2 < NK) load_stage(i + 2);

        const uint32_t Ab = sb + (i % STAGES) * STAGE_BYTES;
        const uint32_t Bb = Ab + 16384;
#pragma unroll
        for (int ks = 0; ks < 2; ks++) {
            const int kch = ks * 2 + lkc;
            const int kcl = 4 + ks * 2 + lkc;
            uint32_t aH[4][4], aL[4][4];
#pragma unroll
            for (int mt = 0; mt < 4; mt++) {
                int row = mw * 64 + mt * 16 + lrow;
                ldsm4(aH[mt], Ab + SWOFF(row, kch));
                ldsm4(aL[mt], Ab + SWOFF(row, kcl));
            }
            // B: K-major -> NON-trans ldmatrix; two x4 groups cover n 0..31
            uint32_t bh[2][4], bl[2][4];
#pragma unroll
            for (int q = 0; q < 2; q++) {
                int br = nw * 32 + q * 16 + lrow;
                ldsm4(bh[q], Bb + SWOFF(br, kch));
                ldsm4(bl[q], Bb + SWOFF(br, kcl));
            }
#pragma unroll
            for (int mt = 0; mt < 4; mt++) {
#pragma unroll
                for (int nt = 0; nt < 4; nt++) {
                    int q = nt >> 1, s2 = nt & 1;
                    uint32_t fh[2] = { bh[q][s2], bh[q][s2 + 2] };
                    uint32_t fl[2] = { bl[q][s2], bl[q][s2 + 2] };
                    mma_bf16(acc[mt][nt], aH[mt], fh);
                    mma_bf16(acc[mt][nt], aH[mt], fl);
                    mma_bf16(acc[mt][nt], aL[mt], fh);
                }
            }
        }
    }

    const int g = lane >> 2, tig = lane & 3;
#pragma unroll
    for (int mt = 0; mt < 4; mt++) {
#pragma unroll
        for (int hh = 0; hh < 2; hh++) {
            int m = row0 + mw * 64 + mt * 16 + g + hh * 8;
            int r = g_rows[m];
            if (r < 0) continue;
            int tok = r & 0xFFFF, slot = (r >> 16) & 1;
            float wgt = g_topw[tok * 2 + slot];
            float* op = &g_outpair[slot][tok][0];
#pragma unroll
            for (int nt = 0; nt < 4; nt++) {
                int col = n0 + nw * 32 + nt * 8 + tig * 2;
                float2 v = make_float2(acc[mt][nt][hh * 2] * wgt,
                                       acc[mt][nt][hh * 2 + 1] * wgt);
                *(float2*)&op[col] = v;
            }
        }
    }
}

// ---------------- 6) combine ----------------
__global__ void combine_kernel(float* __restrict__ out) {
    size_t i = (size_t)blockIdx.x * blockDim.x + threadIdx.x;
    const float4* p0 = (const float4*)&g_outpair[0][0][0];
    const float4* p1 = (const float4*)&g_outpair[1][0][0];
    float4 a = p0[i], b = p1[i];
    ((float4*)out)[i] = make_float4(a.x + b.x, a.y + b.y, a.z + b.z, a.w + b.w);
}

extern "C" void kernel_launch(void* const* d_in, const int* in_sizes, int n_in,
                              void* d_out, int out_size) {
    const float* x  = (const float*)d_in[0];
    const float* gw = (const float*)d_in[1];
    const float* gb = (const float*)d_in[2];
    const float* w1 = (const float*)d_in[3];
    const float* w2 = (const float*)d_in[4];
    const float* w3 = (const float*)d_in[5];
    float* out = (float*)d_out;

    cudaFuncSetAttribute(gemm1_mma, cudaFuncAttributeMaxDynamicSharedMemorySize, SMEM_BYTES);
    cudaFuncSetAttribute(gemm2_mma, cudaFuncAttributeMaxDynamicSharedMemorySize, SMEM_BYTES);

    convert_weights<<<(3 * (NW / 4) + 255) / 256, 256>>>(w1, w2, w3);
    router_kernel<<<T_TOK / 8, 256>>>(x, gw, gb);
    build_lists_kernel<<<1, 1024>>>();
    gather_a<<<ROWCAP, 256>>>(x);
    gemm1_mma<<<dim3(IDIM / 64, ROWCAP / MT), 256, SMEM_BYTES>>>();   // (56, 136)
    gemm2_mma<<<dim3(HDIM / 128, ROWCAP / MT), 256, SMEM_BYTES>>>();  // (8, 136)
    combine_kernel<<<(T_TOK * HDIM / 4) / 256, 256>>>(out);
}

// round 16
// speedup vs baseline: 3.6226x; 1.1078x over previous
#include <cuda_runtime.h>
#include <cuda_bf16.h>
#include <math.h>
#include <stdint.h>

#define T_TOK 8192
#define HDIM  1024
#define IDIM  3584
#define NEXP  8
#define MT    128
#define ROWCAP (2*T_TOK + NEXP*MT)     // 17408
#define NW    (NEXP*IDIM*HDIM)         // 29360128 elems per weight tensor

// ---------------- static scratch ----------------
__device__ __align__(128) __nv_bfloat16 g_w1h[NW], g_w1l[NW];
__device__ __align__(128) __nv_bfloat16 g_w3h[NW], g_w3l[NW];
__device__ __align__(128) __nv_bfloat16 g_w2h[NW], g_w2l[NW];
__device__ __align__(128) __nv_bfloat16 g_ah[(size_t)ROWCAP * HDIM], g_al[(size_t)ROWCAP * HDIM];
__device__ __align__(128) __nv_bfloat16 g_hh[(size_t)ROWCAP * IDIM], g_hl[(size_t)ROWCAP * IDIM];
__device__ float g_outpair[2][T_TOK][HDIM];
__device__ int   g_rows[ROWCAP];        // token | (slot<<16), -1 = pad
__device__ int   g_texp[T_TOK * 2];
__device__ float g_topw[T_TOK * 2];
__device__ int   g_off[NEXP + 1];

// ---------------- helpers (compute_80-era PTX only) ----------------
__device__ __forceinline__ uint32_t smem_u32(const void* p) {
    uint32_t a;
    asm("{ .reg .u64 t; cvta.to.shared.u64 t, %1; cvt.u32.u64 %0, t; }" : "=r"(a) : "l"(p));
    return a;
}
__device__ __forceinline__ void cpasync16(uint32_t dst, const void* src) {
    asm volatile("cp.async.cg.shared.global [%0], [%1], 16;" :: "r"(dst), "l"(src));
}
__device__ __forceinline__ void cp_commit() {
    asm volatile("cp.async.commit_group;" ::: "memory");
}
template<int N>
__device__ __forceinline__ void cp_wait() {
    asm volatile("cp.async.wait_group %0;" :: "n"(N) : "memory");
}
__device__ __forceinline__ void ldsm4(uint32_t* r, uint32_t addr) {
    asm volatile("ldmatrix.sync.aligned.m8n8.x4.shared.b16 {%0,%1,%2,%3}, [%4];"
                 : "=r"(r[0]), "=r"(r[1]), "=r"(r[2]), "=r"(r[3]) : "r"(addr));
}
__device__ __forceinline__ void mma_bf16(float* d, const uint32_t* a, const uint32_t* b) {
    asm volatile("mma.sync.aligned.m16n8k16.row.col.f32.bf16.bf16.f32 "
                 "{%0,%1,%2,%3}, {%4,%5,%6,%7}, {%8,%9}, {%0,%1,%2,%3};"
                 : "+f"(d[0]), "+f"(d[1]), "+f"(d[2]), "+f"(d[3])
                 : "r"(a[0]), "r"(a[1]), "r"(a[2]), "r"(a[3]), "r"(b[0]), "r"(b[1]));
}
__device__ __forceinline__ void split_pair(float a, float b, __nv_bfloat162& hi, __nv_bfloat162& lo) {
    __nv_bfloat16 ah = __float2bfloat16(a);
    __nv_bfloat16 bh = __float2bfloat16(b);
    __nv_bfloat16 al = __float2bfloat16(a - __bfloat162float(ah));
    __nv_bfloat16 bl = __float2bfloat16(b - __bfloat162float(bh));
    hi = __halves2bfloat162(ah, bh);
    lo = __halves2bfloat162(al, bl);
}
__device__ __forceinline__ int find_expert(int row0) {
    int e = 0;
#pragma unroll
    for (int q = 0; q < NEXP; q++)
        if (row0 >= g_off[q + 1]) e = q + 1;
    return e;
}

// K-chunk 64: stage = A(2 blocks of 16KB) + B(2 blocks of 16KB) = 64KB, 3 stages.
// Block layout (16KB): 128 rows x 128B; chunk c 0-3 = hi-plane k 0..31, 4-7 = lo-plane.
// Chunk c of row r at byte (c ^ (r&7))*16 within the row (Swizzle<3,4,3>).
#define STAGES      3
#define BLK         16384
#define STAGE_BYTES (4 * BLK)
#define SMEM_BYTES  (STAGES * STAGE_BYTES)
#define SWOFF(row, c) ((uint32_t)((row) * 128 + (((c) ^ ((row) & 7)) << 4)))

// ---------------- 0) fp32 -> bf16 hi/lo split of all weights ----------------
__global__ void convert_weights(const float* __restrict__ w1,
                                const float* __restrict__ w2,
                                const float* __restrict__ w3) {
    const size_t QT = NW / 4;
    size_t q = (size_t)blockIdx.x * blockDim.x + threadIdx.x;
    if (q >= 3 * QT) return;
    const float* src; __nv_bfloat16 *dh, *dl;
    size_t j = q;
    if (j < QT)           { src = w1; dh = g_w1h; dl = g_w1l; }
    else if (j < 2 * QT)  { j -= QT;     src = w3; dh = g_w3h; dl = g_w3l; }
    else                  { j -= 2 * QT; src = w2; dh = g_w2h; dl = g_w2l; }
    float4 v = ((const float4*)src)[j];
    __nv_bfloat162 h0, l0, h1, l1;
    split_pair(v.x, v.y, h0, l0);
    split_pair(v.z, v.w, h1, l1);
    ((__nv_bfloat162*)dh)[2 * j]     = h0;
    ((__nv_bfloat162*)dh)[2 * j + 1] = h1;
    ((__nv_bfloat162*)dl)[2 * j]     = l0;
    ((__nv_bfloat162*)dl)[2 * j + 1] = l1;
}

// ---------------- 1) Router ----------------
__global__ void router_kernel(const float* __restrict__ x,
                              const float* __restrict__ gw,
                              const float* __restrict__ gb) {
    __shared__ float sgw[NEXP * HDIM];
    for (int i = threadIdx.x; i < NEXP * HDIM; i += blockDim.x) sgw[i] = gw[i];
    __syncthreads();

    int warp = (blockIdx.x * blockDim.x + threadIdx.x) >> 5;
    int lane = threadIdx.x & 31;
    if (warp >= T_TOK) return;

    const float* xr = x + (size_t)warp * HDIM;
    float acc[NEXP];
#pragma unroll
    for (int e = 0; e < NEXP; e++) acc[e] = 0.f;
    for (int k = lane; k < HDIM; k += 32) {
        float xv = xr[k];
#pragma unroll
        for (int e = 0; e < NEXP; e++) acc[e] = fmaf(xv, sgw[e * HDIM + k], acc[e]);
    }
#pragma unroll
    for (int e = 0; e < NEXP; e++) {
#pragma unroll
        for (int o = 16; o > 0; o >>= 1) acc[e] += __shfl_xor_sync(0xffffffffu, acc[e], o);
    }
    if (lane == 0) {
        float mx = -1e30f;
#pragma unroll
        for (int e = 0; e < NEXP; e++) { acc[e] += gb[e]; mx = fmaxf(mx, acc[e]); }
        float se = 0.f;
#pragma unroll
        for (int e = 0; e < NEXP; e++) { acc[e] = expf(acc[e] - mx); se += acc[e]; }
        float inv = 1.f / se;
        float b0 = -1.f, b1 = -1.f; int i0 = 0, i1 = 0;
#pragma unroll
        for (int e = 0; e < NEXP; e++) {
            float p = acc[e] * inv;
            if (p > b0)      { b1 = b0; i1 = i0; b0 = p; i0 = e; }
            else if (p > b1) { b1 = p;  i1 = e; }
        }
        g_texp[warp * 2 + 0] = i0;  g_texp[warp * 2 + 1] = i1;
        g_topw[warp * 2 + 0] = b0;  g_topw[warp * 2 + 1] = b1;
    }
}

// ---------------- 2) Build 128-padded per-expert row lists ----------------
__global__ void build_lists_kernel() {
    __shared__ int cnt[NEXP], off[NEXP + 1], fill[NEXP];
    int tid = threadIdx.x;
    if (tid < NEXP) cnt[tid] = 0;
    __syncthreads();
    for (int i = tid; i < 2 * T_TOK; i += blockDim.x) atomicAdd(&cnt[g_texp[i]], 1);
    __syncthreads();
    if (tid == 0) {
        int o = 0;
        for (int e = 0; e < NEXP; e++) { off[e] = o; o += ((cnt[e] + MT - 1) / MT) * MT; }
        off[NEXP] = o;
    }
    __syncthreads();
    if (tid < NEXP)  fill[tid] = 0;
    if (tid <= NEXP) g_off[tid] = off[tid];
    for (int i = tid; i < ROWCAP; i += blockDim.x) g_rows[i] = -1;
    __syncthreads();
    for (int i = tid; i < 2 * T_TOK; i += blockDim.x) {
        int e = g_texp[i];
        int p = atomicAdd(&fill[e], 1);
        g_rows[off[e] + p] = (i >> 1) | ((i & 1) << 16);
    }
}

// ---------------- 3) gather+split activations ----------------
__global__ void gather_a(const float* __restrict__ x) {
    int row = blockIdx.x;
    int t = threadIdx.x;
    int r = g_rows[row];
    float4 v = make_float4(0.f, 0.f, 0.f, 0.f);
    if (r >= 0) v = ((const float4*)(x + (size_t)(r & 0xFFFF) * HDIM))[t];
    __nv_bfloat162 h0, l0, h1, l1;
    split_pair(v.x, v.y, h0, l0);
    split_pair(v.z, v.w, h1, l1);
    size_t base = (size_t)row * (HDIM / 2) + t * 2;
    ((__nv_bfloat162*)g_ah)[base]     = h0;
    ((__nv_bfloat162*)g_ah)[base + 1] = h1;
    ((__nv_bfloat162*)g_al)[base]     = l0;
    ((__nv_bfloat162*)g_al)[base + 1] = l1;
}

// fragment sets (ping-pong, one per k-step)
struct Frag1 { uint32_t aH[4][4], aL[4][4], b1h[4], b1l[4], b3h[4], b3l[4]; };
struct Frag2 { uint32_t aH[4][4], aL[4][4], bh[2][4], bl[2][4]; };

// ---------------- 4) GEMM1: h = silu(A@w1^T) * (A@w3^T) ----------------
__global__ __launch_bounds__(256, 1) void gemm1_mma() {
    extern __shared__ char smem[];
    const uint32_t sb = smem_u32(smem);
    const int tid = threadIdx.x;
    const int row0 = blockIdx.y * MT;
    const int n0   = blockIdx.x * 64;
    if (row0 >= g_off[NEXP]) return;
    const int e = find_expert(row0);

    const __nv_bfloat16* Ah = g_ah + (size_t)row0 * HDIM;
    const __nv_bfloat16* Al = g_al + (size_t)row0 * HDIM;
    const size_t wb = ((size_t)e * IDIM + n0) * HDIM;
    const __nv_bfloat16* W1h = g_w1h + wb;
    const __nv_bfloat16* W1l = g_w1l + wb;
    const __nv_bfloat16* W3h = g_w3h + wb;
    const __nv_bfloat16* W3l = g_w3l + wb;

    // one slice = one 16KB block (1024 chunks = 4 cp.async per thread)
    auto slice_A = [&](int s, int kb) {
        const uint32_t d = sb + (s % STAGES) * STAGE_BYTES + kb * BLK;
        const int kbase = s * 64 + kb * 32;
#pragma unroll
        for (int i = 0; i < 4; i++) {
            int idx = tid + i * 256;
            int r = idx >> 3, c = idx & 7;
            const __nv_bfloat16* src = ((c < 4) ? Ah : Al) + (size_t)r * HDIM + kbase + (c & 3) * 8;
            cpasync16(d + SWOFF(r, c), src);
        }
    };
    auto slice_B = [&](int s, int kb) {
        const uint32_t d = sb + (s % STAGES) * STAGE_BYTES + 2 * BLK + kb * BLK;
        const int kbase = s * 64 + kb * 32;
#pragma unroll
        for (int i = 0; i < 4; i++) {
            int idx = tid + i * 256;
            int r = idx >> 3, c = idx & 7;
            int rr = r & 63;
            const __nv_bfloat16* mh = (r < 64) ? W1h : W3h;
            const __nv_bfloat16* ml = (r < 64) ? W1l : W3l;
            const __nv_bfloat16* src = ((c < 4) ? mh : ml) + (size_t)rr * HDIM + kbase + (c & 3) * 8;
            cpasync16(d + SWOFF(r, c), src);
        }
    };
    auto load_stage = [&](int s) { slice_A(s, 0); slice_A(s, 1); slice_B(s, 0); slice_B(s, 1); cp_commit(); };

    const int lane = tid & 31, w = tid >> 5;
    const int mw = w >> 2, nw = w & 3;
    const int lrow = lane & 15, lkc = lane >> 4;

    auto frag_load = [&](uint32_t stg, int ks, Frag1& f) {
        const int kb = ks >> 1, ks2 = ks & 1;
        const int kch = ks2 * 2 + lkc, kcl = 4 + ks2 * 2 + lkc;
        const uint32_t Ab = stg + kb * BLK;
        const uint32_t Bb = stg + 2 * BLK + kb * BLK;
#pragma unroll
        for (int mt = 0; mt < 4; mt++) {
            int row = mw * 64 + mt * 16 + lrow;
            ldsm4(f.aH[mt], Ab + SWOFF(row, kch));
            ldsm4(f.aL[mt], Ab + SWOFF(row, kcl));
        }
        int br1 = nw * 16 + lrow, br3 = 64 + nw * 16 + lrow;
        ldsm4(f.b1h, Bb + SWOFF(br1, kch));
        ldsm4(f.b1l, Bb + SWOFF(br1, kcl));
        ldsm4(f.b3h, Bb + SWOFF(br3, kch));
        ldsm4(f.b3l, Bb + SWOFF(br3, kcl));
    };

    float c1[4][2][4] = {}, c3[4][2][4] = {};
    auto do_mma = [&](Frag1& f) {
#pragma unroll
        for (int mt = 0; mt < 4; mt++) {
#pragma unroll
            for (int nt = 0; nt < 2; nt++) {
                uint32_t f1h[2] = { f.b1h[nt], f.b1h[nt + 2] };
                uint32_t f1l[2] = { f.b1l[nt], f.b1l[nt + 2] };
                mma_bf16(c1[mt][nt], f.aH[mt], f1h);
                mma_bf16(c1[mt][nt], f.aH[mt], f1l);
                mma_bf16(c1[mt][nt], f.aL[mt], f1h);
                uint32_t f3h[2] = { f.b3h[nt], f.b3h[nt + 2] };
                uint32_t f3l[2] = { f.b3l[nt], f.b3l[nt + 2] };
                mma_bf16(c3[mt][nt], f.aH[mt], f3h);
                mma_bf16(c3[mt][nt], f.aH[mt], f3l);
                mma_bf16(c3[mt][nt], f.aL[mt], f3h);
            }
        }
    };

    const int NK = HDIM / 64;                  // 16
    load_stage(0); load_stage(1);

    Frag1 f[2];
    for (int i = 0; i < NK; i++) {
        if (i + 2 < NK) cp_wait<1>(); else cp_wait<0>();
        __syncthreads();
        const uint32_t stg = sb + (i % STAGES) * STAGE_BYTES;
        const bool pf = (i + 2 < NK);
        frag_load(stg, 0, f[0]);
#pragma unroll
        for (int ks = 0; ks < 4; ks++) {
            if (ks < 3) frag_load(stg, ks + 1, f[(ks + 1) & 1]);
            if (pf) {                                    // spread prefetch slices
                if (ks == 0) slice_A(i + 2, 0);
                else if (ks == 1) slice_A(i + 2, 1);
                else if (ks == 2) slice_B(i + 2, 0);
                else { slice_B(i + 2, 1); cp_commit(); }
            }
            do_mma(f[ks & 1]);
        }
    }

    // epilogue: silu(c1)*c3 -> bf16 hi/lo planes of h
    const int g = lane >> 2, tig = lane & 3;
#pragma unroll
    for (int mt = 0; mt < 4; mt++) {
#pragma unroll
        for (int nt = 0; nt < 2; nt++) {
            int icol = n0 + nw * 16 + nt * 8 + tig * 2;
#pragma unroll
            for (int hh = 0; hh < 2; hh++) {
                size_t m = (size_t)(row0 + mw * 64 + mt * 16 + g + hh * 8);
                float v1a = c1[mt][nt][hh * 2],     v3a = c3[mt][nt][hh * 2];
                float v1b = c1[mt][nt][hh * 2 + 1], v3b = c3[mt][nt][hh * 2 + 1];
                float ha = v1a / (1.f + expf(-v1a)) * v3a;
                float hb = v1b / (1.f + expf(-v1b)) * v3b;
                __nv_bfloat162 hi, lo;
                split_pair(ha, hb, hi, lo);
                *(__nv_bfloat162*)&g_hh[m * IDIM + icol] = hi;
                *(__nv_bfloat162*)&g_hl[m * IDIM + icol] = lo;
            }
        }
    }
}

// ---------------- 5) GEMM2: outpair = w * (h @ w2^T) ----------------
__global__ __launch_bounds__(256, 1) void gemm2_mma() {
    extern __shared__ char smem[];
    const uint32_t sb = smem_u32(smem);
    const int tid = threadIdx.x;
    const int row0 = blockIdx.y * MT;
    const int n0   = blockIdx.x * 128;
    if (row0 >= g_off[NEXP]) return;
    const int e = find_expert(row0);

    const __nv_bfloat16* Ahp = g_hh + (size_t)row0 * IDIM;
    const __nv_bfloat16* Alp = g_hl + (size_t)row0 * IDIM;
    const size_t wb = ((size_t)e * HDIM + n0) * IDIM;
    const __nv_bfloat16* Bh = g_w2h + wb;
    const __nv_bfloat16* Bl = g_w2l + wb;

    auto slice_A = [&](int s, int kb) {
        const uint32_t d = sb + (s % STAGES) * STAGE_BYTES + kb * BLK;
        const int kbase = s * 64 + kb * 32;
#pragma unroll
        for (int i = 0; i < 4; i++) {
            int idx = tid + i * 256;
            int r = idx >> 3, c = idx & 7;
            const __nv_bfloat16* src = ((c < 4) ? Ahp : Alp) + (size_t)r * IDIM + kbase + (c & 3) * 8;
            cpasync16(d + SWOFF(r, c), src);
        }
    };
    auto slice_B = [&](int s, int kb) {
        const uint32_t d = sb + (s % STAGES) * STAGE_BYTES + 2 * BLK + kb * BLK;
        const int kbase = s * 64 + kb * 32;
#pragma unroll
        for (int i = 0; i < 4; i++) {
            int idx = tid + i * 256;
            int r = idx >> 3, c = idx & 7;
            const __nv_bfloat16* src = ((c < 4) ? Bh : Bl) + (size_t)r * IDIM + kbase + (c & 3) * 8;
            cpasync16(d + SWOFF(r, c), src);
        }
    };
    auto load_stage = [&](int s) { slice_A(s, 0); slice_A(s, 1); slice_B(s, 0); slice_B(s, 1); cp_commit(); };

    const int lane = tid & 31, w = tid >> 5;
    const int mw = w >> 2, nw = w & 3;
    const int lrow = lane & 15, lkc = lane >> 4;

    auto frag_load = [&](uint32_t stg, int ks, Frag2& f) {
        const int kb = ks >> 1, ks2 = ks & 1;
        const int kch = ks2 * 2 + lkc, kcl = 4 + ks2 * 2 + lkc;
        const uint32_t Ab = stg + kb * BLK;
        const uint32_t Bb = stg + 2 * BLK + kb * BLK;
#pragma unroll
        for (int mt = 0; mt < 4; mt++) {
            int row = mw * 64 + mt * 16 + lrow;
            ldsm4(f.aH[mt], Ab + SWOFF(row, kch));
            ldsm4(f.aL[mt], Ab + SWOFF(row, kcl));
        }
#pragma unroll
        for (int q = 0; q < 2; q++) {
            int br = nw * 32 + q * 16 + lrow;
            ldsm4(f.bh[q], Bb + SWOFF(br, kch));
            ldsm4(f.bl[q], Bb + SWOFF(br, kcl));
        }
    };

    float acc[4][4][4] = {};
    auto do_mma = [&](Frag2& f) {
#pragma unroll
        for (int mt = 0; mt < 4; mt++) {
#pragma unroll
            for (int nt = 0; nt < 4; nt++) {
                int q = nt >> 1, s2 = nt & 1;
                uint32_t fh[2] = { f.bh[q][s2], f.bh[q][s2 + 2] };
                uint32_t fl[2] = { f.bl[q][s2], f.bl[q][s2 + 2] };
                mma_bf16(acc[mt][nt], f.aH[mt], fh);
                mma_bf16(acc[mt][nt], f.aH[mt], fl);
                mma_bf16(acc[mt][nt], f.aL[mt], fh);
            }
        }
    };

    const int NK = IDIM / 64;                  // 56
    load_stage(0); load_stage(1);

    Frag2 f[2];
    for (int i = 0; i < NK; i++) {
        if (i + 2 < NK) cp_wait<1>(); else cp_wait<0>();
        __syncthreads();
        const uint32_t stg = sb + (i % STAGES) * STAGE_BYTES;
        const bool pf = (i + 2 < NK);
        frag_load(stg, 0, f[0]);
#pragma unroll
        for (int ks = 0; ks < 4; ks++) {
            if (ks < 3) frag_load(stg, ks + 1, f[(ks + 1) & 1]);
            if (pf) {
                if (ks == 0) slice_A(i + 2, 0);
                else if (ks == 1) slice_A(i + 2, 1);
                else if (ks == 2) slice_B(i + 2, 0);
                else { slice_B(i + 2, 1); cp_commit(); }
            }
            do_mma(f[ks & 1]);
        }
    }

    const int g = lane >> 2, tig = lane & 3;
#pragma unroll
    for (int mt = 0; mt < 4; mt++) {
#pragma unroll
        for (int hh = 0; hh < 2; hh++) {
            int m = row0 + mw * 64 + mt * 16 + g + hh * 8;
            int r = g_rows[m];
            if (r < 0) continue;
            int tok = r & 0xFFFF, slot = (r >> 16) & 1;
            float wgt = g_topw[tok * 2 + slot];
            float* op = &g_outpair[slot][tok][0];
#pragma unroll
            for (int nt = 0; nt < 4; nt++) {
                int col = n0 + nw * 32 + nt * 8 + tig * 2;
                float2 v = make_float2(acc[mt][nt][hh * 2] * wgt,
                                       acc[mt][nt][hh * 2 + 1] * wgt);
                *(float2*)&op[col] = v;
            }
        }
    }
}

// ---------------- 6) combine ----------------
__global__ void combine_kernel(float* __restrict__ out) {
    size_t i = (size_t)blockIdx.x * blockDim.x + threadIdx.x;
    const float4* p0 = (const float4*)&g_outpair[0][0][0];
    const float4* p1 = (const float4*)&g_outpair[1][0][0];
    float4 a = p0[i], b = p1[i];
    ((float4*)out)[i] = make_float4(a.x + b.x, a.y + b.y, a.z + b.z, a.w + b.w);
}

extern "C" void kernel_launch(void* const* d_in, const int* in_sizes, int n_in,
                              void* d_out, int out_size) {
    const float* x  = (const float*)d_in[0];
    const float* gw = (const float*)d_in[1];
    const float* gb = (const float*)d_in[2];
    const float* w1 = (const float*)d_in[3];
    const float* w2 = (const float*)d_in[4];
    const float* w3 = (const float*)d_in[5];
    float* out = (float*)d_out;

    cudaFuncSetAttribute(gemm1_mma, cudaFuncAttributeMaxDynamicSharedMemorySize, SMEM_BYTES);
    cudaFuncSetAttribute(gemm2_mma, cudaFuncAttributeMaxDynamicSharedMemorySize, SMEM_BYTES);

    convert_weights<<<(3 * (NW / 4) + 255) / 256, 256>>>(w1, w2, w3);
    router_kernel<<<T_TOK / 8, 256>>>(x, gw, gb);
    build_lists_kernel<<<1, 1024>>>();
    gather_a<<<ROWCAP, 256>>>(x);
    gemm1_mma<<<dim3(IDIM / 64, ROWCAP / MT), 256, SMEM_BYTES>>>();   // (56, 136)
    gemm2_mma<<<dim3(HDIM / 128, ROWCAP / MT), 256, SMEM_BYTES>>>();  // (8, 136)
    combine_kernel<<<(T_TOK * HDIM / 4) / 256, 256>>>(out);
}